// round 16
// baseline (speedup 1.0000x reference)
#include <cuda_runtime.h>
#include <cuda_bf16.h>
#include <cstdint>

// ============================================================================
// output = 100/512 * (#pos edges with logit<=0.5 + #neg edges with logit>0.5)
// logit = W2 . relu(W1 . relu(x_i*x_j) + b1) + b2.
// (mean of segment sums == total/NUM_GRAPHS => `batch` irrelevant.)
//
// R16: m=3 rows-per-warp (48), 320 threads, TILE_M=480. Cuts B-ldsm bytes per
// edge 33% vs R12 (L1 was the binding resource: R15 m=1 -> L1 87%, tensor 34%;
// R12 m=2 -> L1 68%, tensor 47% with rt~8 implied). Warp-private single-buffer
// A slices, no inter-tile CTA barriers, depth-2 gather pipeline (30 steps).
// ============================================================================

#define NUM_GRAPHS 512
#define HDIM 160
#define TILE_M 480
#define NTHREADS 320          // 10 warps x 48 rows
#define ROWB 336              // padded row pitch (bytes): conflict-free ldsm

// ---- device state (no cudaMalloc allowed) ----
__device__ __nv_bfloat16 g_xbf[16000000];   // 100000 x 160 bf16 = 32MB
__device__ int g_count = 0;
__device__ int g_done  = 0;

// ---- dynamic SMEM layout (bytes) ----
#define OFF_A    0                          // 480 x 336 = 161280
#define OFF_B    161280                     // 160 x 336 = 53760
#define OFF_BW   215040                     // float2[160] {b1,w2} = 1280
#define SMEM_TOTAL 216320

__device__ __forceinline__ uint32_t smem_u32(const void* p) {
    uint32_t a;
    asm("{ .reg .u64 t; cvta.to.shared.u64 t, %1; cvt.u32.u64 %0, t; }"
        : "=r"(a) : "l"(p));
    return a;
}

__device__ __forceinline__ void ldsm_x4(uint32_t* r, uint32_t addr) {
    asm volatile("ldmatrix.sync.aligned.m8n8.x4.shared.b16 {%0,%1,%2,%3}, [%4];"
                 : "=r"(r[0]), "=r"(r[1]), "=r"(r[2]), "=r"(r[3]) : "r"(addr));
}

__device__ __forceinline__ void mma16816(float* d, const uint32_t* a,
                                         const uint32_t* b) {
    asm volatile(
        "mma.sync.aligned.m16n8k16.row.col.f32.bf16.bf16.f32 "
        "{%0,%1,%2,%3}, {%4,%5,%6,%7}, {%8,%9}, {%0,%1,%2,%3};"
        : "+f"(d[0]), "+f"(d[1]), "+f"(d[2]), "+f"(d[3])
        : "r"(a[0]), "r"(a[1]), "r"(a[2]), "r"(a[3]), "r"(b[0]), "r"(b[1]));
}

// bf16x2 multiply + relu, packed
__device__ __forceinline__ uint32_t bfmr(uint32_t a, uint32_t b) {
    __nv_bfloat162 x = *reinterpret_cast<__nv_bfloat162*>(&a);
    __nv_bfloat162 y = *reinterpret_cast<__nv_bfloat162*>(&b);
    __nv_bfloat162 z = __hmul2(x, y);
    const __nv_bfloat162 zero = __float2bfloat162_rn(0.0f);
    z = __hmax2(z, zero);
    return *reinterpret_cast<uint32_t*>(&z);
}

// gather: each warp owns 48 edges (rows wid*48..+47). 30 steps per tile:
// step t in [0,30): edge-in-warp eo = (t/5)*8 + (lid>>2), chunk ch =
// (t%5)*4 + (lid&3). Lane quads read 64B contiguous per side.
// Edge indices: myI0/myJ0 lanes 0..31 = edges 0..31; myI1/myJ1 lanes 0..15
// = edges 32..47.
#define G_EO(t) (((t) / 5) * 8 + (lid >> 2))
#define G_CH(t) (((t) % 5) * 4 + (lid & 3))

#define GLOAD(t, VA, VB) do {                                     \
    int _eo = G_EO(t);                                            \
    int _ch = G_CH(t);                                            \
    int _i0 = __shfl_sync(0xFFFFFFFFu, myI0, _eo & 31);           \
    int _j0 = __shfl_sync(0xFFFFFFFFu, myJ0, _eo & 31);           \
    int _i1 = __shfl_sync(0xFFFFFFFFu, myI1, _eo & 31);           \
    int _j1 = __shfl_sync(0xFFFFFFFFu, myJ1, _eo & 31);           \
    int _ii = (_eo < 32) ? _i0 : _i1;                             \
    int _jj = (_eo < 32) ? _j0 : _j1;                             \
    VA = xrows[(size_t)_ii * 20 + _ch];                           \
    VB = xrows[(size_t)_jj * 20 + _ch];                           \
} while (0)

#define GSTORE(t, VA, VB) do {                                    \
    int _eo = G_EO(t);                                            \
    int _ch = G_CH(t);                                            \
    uint4 _r;                                                     \
    _r.x = bfmr((VA).x, (VB).x);                                  \
    _r.y = bfmr((VA).y, (VB).y);                                  \
    _r.z = bfmr((VA).z, (VB).z);                                  \
    _r.w = bfmr((VA).w, (VB).w);                                  \
    *reinterpret_cast<uint4*>(smem + dstOff + _eo * ROWB + _ch * 16) = _r; \
} while (0)

// pipelined gather step: store stage t, load stage t+2
#define GSTEP(t) do {                                             \
    GSTORE((t), va[(t) & 1], vb[(t) & 1]);                        \
    if ((t) + 2 < 30) GLOAD((t) + 2, va[(t) & 1], vb[(t) & 1]);   \
} while (0)

// load the 20 B-fragment regs for column-chunk j (5x ldsm.x4)
__device__ __forceinline__ void load_b20(uint32_t* br, uint32_t bBase, int j) {
    const uint32_t bj = bBase + (uint32_t)(j * 8 * ROWB);
    #pragma unroll
    for (int t = 0; t < 5; ++t) ldsm_x4(br + 4 * t, bj + (uint32_t)(t * 64));
}

// ============================================================================
// Kernel 0: convert x -> bf16 scratch, zero counter
// ============================================================================
__global__ void cvt_kernel(const float* __restrict__ x, int n4) {
    if (blockIdx.x == 0 && threadIdx.x == 0) g_count = 0;
    int stride = gridDim.x * blockDim.x;
    uint2* out = reinterpret_cast<uint2*>(g_xbf);
    const float4* in = reinterpret_cast<const float4*>(x);
    for (int i = blockIdx.x * blockDim.x + threadIdx.x; i < n4; i += stride) {
        float4 v = in[i];
        __nv_bfloat162 p0 = __floats2bfloat162_rn(v.x, v.y);
        __nv_bfloat162 p1 = __floats2bfloat162_rn(v.z, v.w);
        uint2 o;
        o.x = *reinterpret_cast<uint32_t*>(&p0);
        o.y = *reinterpret_cast<uint32_t*>(&p1);
        out[i] = o;
    }
}

// ============================================================================
// Kernel 1: persistent fused edge-MLP + misclassification count + output
// ============================================================================
__global__ void __launch_bounds__(NTHREADS, 1)
gae_main_kernel(const int* __restrict__ pos, const int* __restrict__ neg,
                const float* __restrict__ W1, const float* __restrict__ b1,
                const float* __restrict__ W2, const float* __restrict__ b2,
                int Ep, int En, float* __restrict__ out) {
    extern __shared__ char smem[];
    const uint32_t sb = smem_u32(smem);
    const int tid = threadIdx.x;
    const int wid = tid >> 5;
    const int lid = tid & 31;
    const int Etot = Ep + En;
    const int ntiles = (Etot + TILE_M - 1) / TILE_M;

    // --- load W1 -> SMEM B [160 rows x 336B pitch], f32 -> bf16 ---
    {
        const float4* w1v = reinterpret_cast<const float4*>(W1);
        for (int idx = tid; idx < 6400; idx += NTHREADS) {
            int n  = idx / 40;
            int kc = idx - n * 40;
            float4 w = w1v[idx];
            __nv_bfloat162 p0 = __floats2bfloat162_rn(w.x, w.y);
            __nv_bfloat162 p1 = __floats2bfloat162_rn(w.z, w.w);
            uint2 v;
            v.x = *reinterpret_cast<uint32_t*>(&p0);
            v.y = *reinterpret_cast<uint32_t*>(&p1);
            *reinterpret_cast<uint2*>(smem + OFF_B + n * ROWB + kc * 8) = v;
        }
    }
    if (tid < HDIM) {
        reinterpret_cast<float2*>(smem + OFF_BW)[tid] = make_float2(b1[tid], W2[tid]);
    }

    const float2* sbw = reinterpret_cast<const float2*>(smem + OFF_BW);
    const uint4* xrows = reinterpret_cast<const uint4*>(g_xbf);  // 20 uint4/row
    const float b2v = b2[0];

    // per-thread ldmatrix address components (warp-private 48-row A slice)
    const uint32_t aBase = sb + OFF_A
        + (uint32_t)((wid * 48 + ((lid >> 3) & 1) * 8 + (lid & 7)) * ROWB
                     + (lid >> 4) * 16);
    const uint32_t dstOff = OFF_A + (uint32_t)(wid * 48 * ROWB);
    const uint32_t bBase = sb + OFF_B
        + (uint32_t)((lid & 7) * ROWB) + (uint32_t)((lid >> 3) * 16);

    int cnt = 0;
    int tile = blockIdx.x;

    __syncthreads();                           // W1/BW ready (only CTA barrier)

    if (tile < ntiles) {
        // ---- prologue: gather this warp's 48-edge slice of the first tile ----
        {
            int myI0 = 0, myJ0 = 0, myI1 = 0, myJ1 = 0;
            {
                int g = tile * TILE_M + wid * 48 + lid;
                if (g < Etot) {
                    if (g < Ep) { myI0 = pos[g]; myJ0 = pos[g + Ep]; }
                    else        { int q = g - Ep; myI0 = neg[q]; myJ0 = neg[q + En]; }
                }
                if (lid < 16) {
                    int g1 = tile * TILE_M + wid * 48 + 32 + lid;
                    if (g1 < Etot) {
                        if (g1 < Ep) { myI1 = pos[g1]; myJ1 = pos[g1 + Ep]; }
                        else         { int q = g1 - Ep; myI1 = neg[q]; myJ1 = neg[q + En]; }
                    }
                }
            }
            #pragma unroll 5
            for (int t = 0; t < 30; ++t) {
                uint4 va, vb;
                GLOAD(t, va, vb);
                GSTORE(t, va, vb);
            }
        }
        __syncwarp();   // order STS before ldsm (warp-private slice)

        for (; tile < ntiles; tile += gridDim.x) {
            // ---- next-tile edge indices (register-resident, per warp) ----
            const int nt = tile + gridDim.x;
            const bool gat = (nt < ntiles);
            int myI0 = 0, myJ0 = 0, myI1 = 0, myJ1 = 0;
            if (gat) {
                int g = nt * TILE_M + wid * 48 + lid;
                if (g < Etot) {
                    if (g < Ep) { myI0 = pos[g]; myJ0 = pos[g + Ep]; }
                    else        { int q = g - Ep; myI0 = neg[q]; myJ0 = neg[q + En]; }
                }
                if (lid < 16) {
                    int g1 = nt * TILE_M + wid * 48 + 32 + lid;
                    if (g1 < Etot) {
                        if (g1 < Ep) { myI1 = pos[g1]; myJ1 = pos[g1 + Ep]; }
                        else         { int q = g1 - Ep; myI1 = neg[q]; myJ1 = neg[q + En]; }
                    }
                }
            }

            // ---- A fragments: this warp's 48 rows, all K (120 regs).
            // All af ldsm results consumed before the first next-tile GSTORE
            // issues (LSU program order) -> single-buffered slice is safe. ----
            uint32_t af[3][10][4];
            #pragma unroll
            for (int m = 0; m < 3; ++m)
                #pragma unroll
                for (int s = 0; s < 10; ++s)
                    ldsm_x4(af[m][s], aBase + (uint32_t)(m * 16 * ROWB + s * 32));

            // ---- depth-2 gather pipeline prefetch ----
            uint4 va[2], vb[2];
            if (gat) { GLOAD(0, va[0], vb[0]); GLOAD(1, va[1], vb[1]); }

            float acc[3][2] = {{0.f,0.f},{0.f,0.f},{0.f,0.f}};
            uint32_t br[20];
            int gs = 0;

            // ---- j-loop: 30 MMAs per B batch; gather 2/j for j<10, 1/j after ----
            #pragma unroll 2
            for (int j = 0; j < 20; ++j) {
                load_b20(br, bBase, j);
                float dd[3][4] = {{0.f,0.f,0.f,0.f},{0.f,0.f,0.f,0.f},
                                  {0.f,0.f,0.f,0.f}};
                #pragma unroll
                for (int s = 0; s < 10; ++s) {
                    const uint32_t* b = br + ((s >> 1) << 2) + ((s & 1) << 1);
                    mma16816(dd[0], af[0][s], b);
                    mma16816(dd[1], af[1][s], b);
                    mma16816(dd[2], af[2][s], b);
                }
                if (gat) {
                    GSTEP(gs); ++gs;
                    if (j < 10) { GSTEP(gs); ++gs; }
                }
                const int n0 = j * 8 + (lid & 3) * 2;
                const float2 bw0 = sbw[n0];
                const float2 bw1 = sbw[n0 + 1];
                #pragma unroll
                for (int m = 0; m < 3; ++m) {
                    acc[m][0] += fmaxf(dd[m][0] + bw0.x, 0.0f) * bw0.y
                               + fmaxf(dd[m][1] + bw1.x, 0.0f) * bw1.y;
                    acc[m][1] += fmaxf(dd[m][2] + bw0.x, 0.0f) * bw0.y
                               + fmaxf(dd[m][3] + bw1.x, 0.0f) * bw1.y;
                }
            }

            // ---- reduce 4 lanes/row, threshold, count ----
            #pragma unroll
            for (int m = 0; m < 3; ++m) {
                #pragma unroll
                for (int h = 0; h < 2; ++h) {
                    float a = acc[m][h];
                    a += __shfl_xor_sync(0xFFFFFFFFu, a, 1);
                    a += __shfl_xor_sync(0xFFFFFFFFu, a, 2);
                    if ((lid & 3) == 0) {
                        int r = tile * TILE_M + wid * 48 + m * 16 + h * 8 + (lid >> 2);
                        if (r < Etot) {
                            bool pred = (a + b2v) > 0.5f;
                            if (pred != (r < Ep)) cnt++;
                        }
                    }
                }
            }
            __syncwarp();   // order this warp's GSTOREs before next ldsm af
        }
    }

    // ---- reduce counts within warp, accumulate globally ----
    #pragma unroll
    for (int o = 16; o; o >>= 1) cnt += __shfl_xor_sync(0xFFFFFFFFu, cnt, o);
    if (lid == 0 && cnt) atomicAdd(&g_count, cnt);

    // ---- last CTA writes the scalar and resets state for the next call ----
    __syncthreads();
    if (tid == 0) {
        __threadfence();
        if (atomicAdd(&g_done, 1) == (int)gridDim.x - 1) {
            int total = atomicAdd(&g_count, 0);
            out[0] = (float)total * 0.1953125f;   // * 100 / 512, exact in f32
            g_count = 0;
            g_done  = 0;
        }
    }
}

// ============================================================================
extern "C" void kernel_launch(void* const* d_in, const int* in_sizes, int n_in,
                              void* d_out, int out_size) {
    const float* x   = (const float*)d_in[0];
    const int*   pos = (const int*)  d_in[1];
    const int*   neg = (const int*)  d_in[2];
    // d_in[3] = batch (irrelevant: mean of segment sums == total/512)
    const float* W1  = (const float*)d_in[4];
    const float* b1  = (const float*)d_in[5];
    const float* W2  = (const float*)d_in[6];
    const float* b2  = (const float*)d_in[7];

    int Ep = in_sizes[1] / 2;
    int En = in_sizes[2] / 2;
    int n4 = in_sizes[0] / 4;

    static int configured = 0;
    if (!configured) {
        cudaFuncSetAttribute(gae_main_kernel,
                             cudaFuncAttributeMaxDynamicSharedMemorySize,
                             SMEM_TOTAL);
        configured = 1;
    }

    int sms = 148;
    cudaDeviceGetAttribute(&sms, cudaDevAttrMultiProcessorCount, 0);
    if (sms <= 0) sms = 148;

    cvt_kernel<<<2048, 256>>>(x, n4);
    gae_main_kernel<<<sms, NTHREADS, SMEM_TOTAL>>>(pos, neg, W1, b1, W2, b2,
                                                   Ep, En, (float*)d_out);
}

// round 17
// speedup vs baseline: 1.7481x; 1.7481x over previous
#include <cuda_runtime.h>
#include <cuda_bf16.h>
#include <cstdint>

// ============================================================================
// output = 100/512 * (#pos edges with logit<=0.5 + #neg edges with logit>0.5)
// logit = W2 . relu(W1 . relu(x_i*x_j) + b1) + b2.
// (mean of segment sums == total/NUM_GRAPHS => `batch` irrelevant.)
//
// R17 = R12 inner loop (bf16 m16n8k16, m=2/32-row warp-private A slices,
// B-fragment double buffer, split-K accumulators, depth-2 gather pipeline,
// no CTA barriers) + PER-WARP ATOMIC WORK-STEALING: each warp pulls 32-edge
// chunk tickets from a global counter, absorbing inter-warp/inter-SM spread
// (B300 spr_max 1.1-2.0x at high MLP_p1) and the static-schedule tail.
// ============================================================================

#define NUM_GRAPHS 512
#define HDIM 160
#define NTHREADS 384          // 12 warps x 32-edge chunks
#define ROWB 336              // padded row pitch (bytes): conflict-free ldsm

// ---- device state (no cudaMalloc allowed) ----
__device__ __nv_bfloat16 g_xbf[16000000];   // 100000 x 160 bf16 = 32MB
__device__ int g_count = 0;
__device__ int g_done  = 0;
__device__ int g_tile  = 0;                 // work-stealing ticket counter

// ---- dynamic SMEM layout (bytes) ----
#define OFF_A    0                          // 384 x 336 = 129024 (12 slices)
#define OFF_B    129024                     // 160 x 336 = 53760
#define OFF_BW   182784                     // float2[160] {b1,w2} = 1280
#define SMEM_TOTAL 184064

__device__ __forceinline__ uint32_t smem_u32(const void* p) {
    uint32_t a;
    asm("{ .reg .u64 t; cvta.to.shared.u64 t, %1; cvt.u32.u64 %0, t; }"
        : "=r"(a) : "l"(p));
    return a;
}

__device__ __forceinline__ void ldsm_x4(uint32_t* r, uint32_t addr) {
    asm volatile("ldmatrix.sync.aligned.m8n8.x4.shared.b16 {%0,%1,%2,%3}, [%4];"
                 : "=r"(r[0]), "=r"(r[1]), "=r"(r[2]), "=r"(r[3]) : "r"(addr));
}

__device__ __forceinline__ void mma16816(float* d, const uint32_t* a,
                                         const uint32_t* b) {
    asm volatile(
        "mma.sync.aligned.m16n8k16.row.col.f32.bf16.bf16.f32 "
        "{%0,%1,%2,%3}, {%4,%5,%6,%7}, {%8,%9}, {%0,%1,%2,%3};"
        : "+f"(d[0]), "+f"(d[1]), "+f"(d[2]), "+f"(d[3])
        : "r"(a[0]), "r"(a[1]), "r"(a[2]), "r"(a[3]), "r"(b[0]), "r"(b[1]));
}

// bf16x2 multiply + relu, packed
__device__ __forceinline__ uint32_t bfmr(uint32_t a, uint32_t b) {
    __nv_bfloat162 x = *reinterpret_cast<__nv_bfloat162*>(&a);
    __nv_bfloat162 y = *reinterpret_cast<__nv_bfloat162*>(&b);
    __nv_bfloat162 z = __hmul2(x, y);
    const __nv_bfloat162 zero = __float2bfloat162_rn(0.0f);
    z = __hmax2(z, zero);
    return *reinterpret_cast<uint32_t*>(&z);
}

// gather: each warp owns a 32-edge chunk (its 32-row slice). it in [0,20):
// eo = edge-in-chunk, ch = uint4 chunk; lane quads read 64B contiguous.
#define G_EO(it) ((lid >> 2) + (((it) / 5) << 3))
#define G_CH(it) (((it) % 5) * 4 + (lid & 3))

#define GLOAD(it, VA, VB) do {                                   \
    int _eo = G_EO(it);                                          \
    int _ch = G_CH(it);                                          \
    int _ii = __shfl_sync(0xFFFFFFFFu, myI, _eo);                \
    int _jj = __shfl_sync(0xFFFFFFFFu, myJ, _eo);                \
    VA = xrows[(size_t)_ii * 20 + _ch];                          \
    VB = xrows[(size_t)_jj * 20 + _ch];                          \
} while (0)

#define GSTORE(it, VA, VB) do {                                  \
    int _eo = G_EO(it);                                          \
    int _ch = G_CH(it);                                          \
    uint4 _r;                                                    \
    _r.x = bfmr((VA).x, (VB).x);                                 \
    _r.y = bfmr((VA).y, (VB).y);                                 \
    _r.z = bfmr((VA).z, (VB).z);                                 \
    _r.w = bfmr((VA).w, (VB).w);                                 \
    *reinterpret_cast<uint4*>(smem + dstOff + _eo * ROWB + _ch * 16) = _r; \
} while (0)

// load the 20 B-fragment regs for column-chunk j (5x ldsm.x4)
__device__ __forceinline__ void load_b20(uint32_t* br, uint32_t bBase, int j) {
    const uint32_t bj = bBase + (uint32_t)(j * 8 * ROWB);
    #pragma unroll
    for (int t = 0; t < 5; ++t) ldsm_x4(br + 4 * t, bj + (uint32_t)(t * 64));
}

// 20 MMAs into 4 independent accumulator chains (RAW distance 4)
__device__ __forceinline__ void mma20(float dd[2][2][4],
                                      const uint32_t af[2][10][4],
                                      const uint32_t* br) {
    #pragma unroll
    for (int s = 0; s < 10; ++s) {
        const uint32_t* b = br + ((s >> 1) << 2) + ((s & 1) << 1);
        mma16816(dd[0][s & 1], af[0][s], b);
        mma16816(dd[1][s & 1], af[1][s], b);
    }
}

__device__ __forceinline__ void epi(float dd[2][2][4], float acc[2][2],
                                    const float2* sbw, int j, int lid) {
    const int n0 = j * 8 + (lid & 3) * 2;
    const float2 bw0 = sbw[n0];
    const float2 bw1 = sbw[n0 + 1];
    #pragma unroll
    for (int m = 0; m < 2; ++m) {
        float d0 = dd[m][0][0] + dd[m][1][0];
        float d1 = dd[m][0][1] + dd[m][1][1];
        float d2 = dd[m][0][2] + dd[m][1][2];
        float d3 = dd[m][0][3] + dd[m][1][3];
        acc[m][0] += fmaxf(d0 + bw0.x, 0.0f) * bw0.y
                   + fmaxf(d1 + bw1.x, 0.0f) * bw1.y;
        acc[m][1] += fmaxf(d2 + bw0.x, 0.0f) * bw0.y
                   + fmaxf(d3 + bw1.x, 0.0f) * bw1.y;
    }
}

#define DD_ZERO(dd) do {                                         \
    _Pragma("unroll")                                            \
    for (int _m = 0; _m < 2; ++_m)                               \
        _Pragma("unroll")                                        \
        for (int _h = 0; _h < 2; ++_h)                           \
            _Pragma("unroll")                                    \
            for (int _r = 0; _r < 4; ++_r) (dd)[_m][_h][_r] = 0.0f; \
} while (0)

// ============================================================================
// Kernel 0: convert x -> bf16 scratch, zero counters
// ============================================================================
__global__ void cvt_kernel(const float* __restrict__ x, int n4) {
    if (blockIdx.x == 0 && threadIdx.x == 0) { g_count = 0; g_tile = 0; }
    int stride = gridDim.x * blockDim.x;
    uint2* out = reinterpret_cast<uint2*>(g_xbf);
    const float4* in = reinterpret_cast<const float4*>(x);
    for (int i = blockIdx.x * blockDim.x + threadIdx.x; i < n4; i += stride) {
        float4 v = in[i];
        __nv_bfloat162 p0 = __floats2bfloat162_rn(v.x, v.y);
        __nv_bfloat162 p1 = __floats2bfloat162_rn(v.z, v.w);
        uint2 o;
        o.x = *reinterpret_cast<uint32_t*>(&p0);
        o.y = *reinterpret_cast<uint32_t*>(&p1);
        out[i] = o;
    }
}

// ============================================================================
// Kernel 1: persistent fused edge-MLP + misclassification count + output
// ============================================================================
__global__ void __launch_bounds__(NTHREADS, 1)
gae_main_kernel(const int* __restrict__ pos, const int* __restrict__ neg,
                const float* __restrict__ W1, const float* __restrict__ b1,
                const float* __restrict__ W2, const float* __restrict__ b2,
                int Ep, int En, float* __restrict__ out) {
    extern __shared__ char smem[];
    const uint32_t sb = smem_u32(smem);
    const int tid = threadIdx.x;
    const int wid = tid >> 5;
    const int lid = tid & 31;
    const int Etot = Ep + En;
    const int nchunks = (Etot + 31) >> 5;      // 32-edge work units

    // --- load W1 -> SMEM B [160 rows x 336B pitch], f32 -> bf16 ---
    {
        const float4* w1v = reinterpret_cast<const float4*>(W1);
        for (int idx = tid; idx < 6400; idx += NTHREADS) {
            int n  = idx / 40;
            int kc = idx - n * 40;
            float4 w = w1v[idx];
            __nv_bfloat162 p0 = __floats2bfloat162_rn(w.x, w.y);
            __nv_bfloat162 p1 = __floats2bfloat162_rn(w.z, w.w);
            uint2 v;
            v.x = *reinterpret_cast<uint32_t*>(&p0);
            v.y = *reinterpret_cast<uint32_t*>(&p1);
            *reinterpret_cast<uint2*>(smem + OFF_B + n * ROWB + kc * 8) = v;
        }
    }
    if (tid < HDIM) {
        reinterpret_cast<float2*>(smem + OFF_BW)[tid] = make_float2(b1[tid], W2[tid]);
    }

    const float2* sbw = reinterpret_cast<const float2*>(smem + OFF_BW);
    const uint4* xrows = reinterpret_cast<const uint4*>(g_xbf);  // 20 uint4/row
    const float b2v = b2[0];

    // per-thread ldmatrix address components (warp-private 32-row A slice)
    const uint32_t aBase = sb + OFF_A
        + (uint32_t)((wid * 32 + ((lid >> 3) & 1) * 8 + (lid & 7)) * ROWB
                     + (lid >> 4) * 16);
    const uint32_t dstOff = OFF_A + (uint32_t)(wid * 32 * ROWB);
    const uint32_t bBase = sb + OFF_B
        + (uint32_t)((lid & 7) * ROWB) + (uint32_t)((lid >> 3) * 16);

    int cnt = 0;

    __syncthreads();                           // W1/BW ready (only CTA barrier)

    // ---- work-stealing: warp pulls 32-edge chunk tickets ----
    int cur;
    {
        int t = 0;
        if (lid == 0) t = atomicAdd(&g_tile, 1);
        cur = __shfl_sync(0xFFFFFFFFu, t, 0);
    }

    if (cur < nchunks) {
        // ---- prologue: gather chunk `cur` into this warp's slice ----
        {
            int g = cur * 32 + lid;
            int myI = 0, myJ = 0;
            if (g < Etot) {
                if (g < Ep) { myI = pos[g];      myJ = pos[g + Ep]; }
                else        { int q = g - Ep; myI = neg[q]; myJ = neg[q + En]; }
            }
            #pragma unroll 4
            for (int it = 0; it < 20; ++it) {
                uint4 va, vb;
                GLOAD(it, va, vb);
                GSTORE(it, va, vb);
            }
        }
        __syncwarp();   // order STS before ldsm (warp-private slice)

        for (;;) {
            // ---- pull next ticket; fetch its edge indices ----
            int nxt;
            {
                int t = 0;
                if (lid == 0) t = atomicAdd(&g_tile, 1);
                nxt = __shfl_sync(0xFFFFFFFFu, t, 0);
            }
            const bool gat = (nxt < nchunks);
            int myI = 0, myJ = 0;
            if (gat) {
                int g = nxt * 32 + lid;
                if (g < Etot) {
                    if (g < Ep) { myI = pos[g];      myJ = pos[g + Ep]; }
                    else        { int q = g - Ep; myI = neg[q]; myJ = neg[q + En]; }
                }
            }

            // ---- A fragments: this warp's 32 rows, all K (80 regs) ----
            uint32_t af[2][10][4];
            #pragma unroll
            for (int m = 0; m < 2; ++m)
                #pragma unroll
                for (int s = 0; s < 10; ++s)
                    ldsm_x4(af[m][s], aBase + (uint32_t)(m * 16 * ROWB + s * 32));

            // ---- depth-2 gather pipeline prefetch ----
            uint4 va[2], vb[2];
            if (gat) { GLOAD(0, va[0], vb[0]); GLOAD(1, va[1], vb[1]); }

            float acc[2][2] = {{0.0f, 0.0f}, {0.0f, 0.0f}};

            // ---- j-loop: B fragments double buffered ----
            uint32_t brA[20], brB[20];
            load_b20(brA, bBase, 0);

            #pragma unroll 2
            for (int jj = 0; jj < 10; ++jj) {
                const int j0 = 2 * jj, j1 = j0 + 1;
                float dd[2][2][4];

                load_b20(brB, bBase, j1);
                DD_ZERO(dd);
                mma20(dd, af, brA);
                if (gat) {
                    GSTORE(j0, va[0], vb[0]);
                    if (j0 + 2 < 20) GLOAD(j0 + 2, va[0], vb[0]);
                }
                epi(dd, acc, sbw, j0, lid);

                if (jj < 9) load_b20(brA, bBase, j0 + 2);
                DD_ZERO(dd);
                mma20(dd, af, brB);
                if (gat) {
                    GSTORE(j1, va[1], vb[1]);
                    if (j1 + 2 < 20) GLOAD(j1 + 2, va[1], vb[1]);
                }
                epi(dd, acc, sbw, j1, lid);
            }

            // ---- reduce 4 lanes/row, threshold, count ----
            #pragma unroll
            for (int m = 0; m < 2; ++m) {
                #pragma unroll
                for (int h = 0; h < 2; ++h) {
                    float a = acc[m][h];
                    a += __shfl_xor_sync(0xFFFFFFFFu, a, 1);
                    a += __shfl_xor_sync(0xFFFFFFFFu, a, 2);
                    if ((lid & 3) == 0) {
                        int r = cur * 32 + m * 16 + h * 8 + (lid >> 2);
                        if (r < Etot) {
                            bool pred = (a + b2v) > 0.5f;
                            if (pred != (r < Ep)) cnt++;
                        }
                    }
                }
            }
            __syncwarp();   // order this warp's GSTOREs before next ldsm af
            if (!gat) break;
            cur = nxt;
        }
    }

    // ---- reduce counts within warp, accumulate globally ----
    #pragma unroll
    for (int o = 16; o; o >>= 1) cnt += __shfl_xor_sync(0xFFFFFFFFu, cnt, o);
    if (lid == 0 && cnt) atomicAdd(&g_count, cnt);

    // ---- last CTA writes the scalar and resets state for the next call ----
    __syncthreads();
    if (tid == 0) {
        __threadfence();
        if (atomicAdd(&g_done, 1) == (int)gridDim.x - 1) {
            int total = atomicAdd(&g_count, 0);
            out[0] = (float)total * 0.1953125f;   // * 100 / 512, exact in f32
            g_count = 0;
            g_done  = 0;
        }
    }
}

// ============================================================================
extern "C" void kernel_launch(void* const* d_in, const int* in_sizes, int n_in,
                              void* d_out, int out_size) {
    const float* x   = (const float*)d_in[0];
    const int*   pos = (const int*)  d_in[1];
    const int*   neg = (const int*)  d_in[2];
    // d_in[3] = batch (irrelevant: mean of segment sums == total/512)
    const float* W1  = (const float*)d_in[4];
    const float* b1  = (const float*)d_in[5];
    const float* W2  = (const float*)d_in[6];
    const float* b2  = (const float*)d_in[7];

    int Ep = in_sizes[1] / 2;
    int En = in_sizes[2] / 2;
    int n4 = in_sizes[0] / 4;

    static int configured = 0;
    if (!configured) {
        cudaFuncSetAttribute(gae_main_kernel,
                             cudaFuncAttributeMaxDynamicSharedMemorySize,
                             SMEM_TOTAL);
        configured = 1;
    }

    int sms = 148;
    cudaDeviceGetAttribute(&sms, cudaDevAttrMultiProcessorCount, 0);
    if (sms <= 0) sms = 148;

    cvt_kernel<<<2048, 256>>>(x, n4);
    gae_main_kernel<<<sms, NTHREADS, SMEM_TOTAL>>>(pos, neg, W1, b1, W2, b2,
                                                   Ep, En, (float*)d_out);
}